// round 11
// baseline (speedup 1.0000x reference)
#include <cuda_runtime.h>
#include <cuda_bf16.h>
#include <cstdint>

// Polynomial attention deg-2, B=2 H=16 S=2048 D=64 fp32.
// GEMM1: bf16 2-term split, mma.m16n8k16 (pair-interleaved K/Q -> LDS.64 frags)
// GEMM2: tf32 m16n8k8, A-frags direct from GEMM1 accumulator; V stored
//        transposed (dim-major) -> uint2 B-frags (key-perm cancels interleave).
// Epilogue (square + rna) fused per key-group into GEMM2 issue stream.

#define NBH 32
#define SLEN 2048
#define DDIM 64
#define BM 256
#define BT 64
#define NITER (SLEN / BT)
#define EPS_CLAMP 1e-4f

#define LDQ2 36
#define LDK2 36
#define LDVT 72

// smem offsets (4-byte units)
#define OF_QH 0
#define OF_QL (OF_QH + BM * LDQ2)
#define OF_KH (OF_QL + BM * LDQ2)          // [2][64][36] u32 (bf16 pairs, interleaved)
#define OF_KL (OF_KH + 2 * BT * LDK2)
#define OF_V  (OF_KL + 2 * BT * LDK2)      // [2][64 dims][LDVT] f32 (V^T)
#define SMEM_U32 (OF_V + 2 * DDIM * LDVT)
#define SMEM_BYTES (SMEM_U32 * 4)

// global scratch
__device__ uint32_t g_KH[(size_t)NBH * SLEN * 32];   // pair-interleaved bf16 splits
__device__ uint32_t g_KL[(size_t)NBH * SLEN * 32];
__device__ float    g_VT[(size_t)NBH * DDIM * SLEN]; // rna-rounded V transposed

__device__ __forceinline__ float tf32_rna(float x) {
    uint32_t u;
    asm("cvt.rna.tf32.f32 %0, %1;" : "=r"(u) : "f"(x));
    return __uint_as_float(u);
}
__device__ __forceinline__ uint32_t packbf(float hi, float lo) {
    uint32_t u;
    asm("cvt.rn.bf16x2.f32 %0, %1, %2;" : "=r"(u) : "f"(hi), "f"(lo));
    return u;
}
__device__ __forceinline__ float bfrt(float x) {
    return __bfloat162float(__float2bfloat16(x));
}
__device__ __forceinline__ uint32_t smem_u32addr(const void* p) {
    uint32_t a;
    asm("{ .reg .u64 t; cvta.to.shared.u64 t, %1; cvt.u32.u64 %0, t; }"
        : "=r"(a) : "l"(p));
    return a;
}
__device__ __forceinline__ void cp16(uint32_t dst, const void* src) {
    asm volatile("cp.async.cg.shared.global [%0], [%1], 16;"
                 :: "r"(dst), "l"(src));
}
__device__ __forceinline__ void mma16(float* d, uint32_t a0, uint32_t a1,
                                      uint32_t a2, uint32_t a3,
                                      uint32_t b0, uint32_t b1) {
    asm("mma.sync.aligned.m16n8k16.row.col.f32.bf16.bf16.f32 "
        "{%0,%1,%2,%3}, {%4,%5,%6,%7}, {%8,%9}, {%0,%1,%2,%3};"
        : "+f"(d[0]), "+f"(d[1]), "+f"(d[2]), "+f"(d[3])
        : "r"(a0), "r"(a1), "r"(a2), "r"(a3), "r"(b0), "r"(b1));
}
__device__ __forceinline__ void mma8v(float* d, float a0, float a1,
                                      float a2, float a3,
                                      uint32_t b0, uint32_t b1) {
    asm("mma.sync.aligned.m16n8k8.row.col.f32.tf32.tf32.f32 "
        "{%0,%1,%2,%3}, {%4,%5,%6,%7}, {%8,%9}, {%0,%1,%2,%3};"
        : "+f"(d[0]), "+f"(d[1]), "+f"(d[2]), "+f"(d[3])
        : "r"(__float_as_uint(a0)), "r"(__float_as_uint(a1)),
          "r"(__float_as_uint(a2)), "r"(__float_as_uint(a3)),
          "r"(b0), "r"(b1));
}

// ---- precompute: K -> pair-interleaved (KH,KL) bf16 packs ----
// thread handles 16 elems = one 8-u32 block; interleave: out[p] = in[sig^-1(p)],
// sig(j)=2(j&3)+(j>>2)  =>  out = {in0,in4,in1,in5, in2,in6,in3,in7}
__global__ void precompute_k(const float* __restrict__ k) {
    size_t i = (size_t)blockIdx.x * blockDim.x + threadIdx.x;
    const float4* k4 = (const float4*)k;
    uint32_t hp[8], lp[8];
#pragma unroll
    for (int r = 0; r < 4; r++) {
        float4 x = k4[i * 4 + r];
        float h0 = bfrt(x.x), h1 = bfrt(x.y), h2 = bfrt(x.z), h3 = bfrt(x.w);
        hp[r * 2 + 0] = packbf(h1, h0);
        hp[r * 2 + 1] = packbf(h3, h2);
        lp[r * 2 + 0] = packbf(x.y - h1, x.x - h0);
        lp[r * 2 + 1] = packbf(x.w - h3, x.z - h2);
    }
    uint4 H0 = make_uint4(hp[0], hp[4], hp[1], hp[5]);
    uint4 H1 = make_uint4(hp[2], hp[6], hp[3], hp[7]);
    uint4 L0 = make_uint4(lp[0], lp[4], lp[1], lp[5]);
    uint4 L1 = make_uint4(lp[2], lp[6], lp[3], lp[7]);
    ((uint4*)g_KH)[i * 2 + 0] = H0;
    ((uint4*)g_KH)[i * 2 + 1] = H1;
    ((uint4*)g_KL)[i * 2 + 0] = L0;
    ((uint4*)g_KL)[i * 2 + 1] = L1;
}

// ---- precompute: V -> rna-rounded transpose g_VT[bh][dim][key] ----
__global__ void build_vt(const float* __restrict__ v) {
    __shared__ float tile[32][65];
    const int bh = blockIdx.y;
    const int t0 = blockIdx.x * 32;
    const int tid = threadIdx.x;
    const float4* v4 = (const float4*)(v + ((size_t)bh * SLEN + t0) * DDIM);
#pragma unroll
    for (int r = 0; r < 2; r++) {
        int i4 = tid + r * 256;
        int t = i4 >> 4, d0 = (i4 & 15) * 4;
        float4 x = v4[i4];
        tile[t][d0 + 0] = x.x; tile[t][d0 + 1] = x.y;
        tile[t][d0 + 2] = x.z; tile[t][d0 + 3] = x.w;
    }
    __syncthreads();
    float* outp = g_VT + (size_t)bh * DDIM * SLEN;
#pragma unroll
    for (int r = 0; r < 2; r++) {
        int i = tid + r * 256;
        int d = i >> 3, j = i & 7;
        float4 y;
        y.x = tf32_rna(tile[j * 4 + 0][d]);
        y.y = tf32_rna(tile[j * 4 + 1][d]);
        y.z = tf32_rna(tile[j * 4 + 2][d]);
        y.w = tf32_rna(tile[j * 4 + 3][d]);
        *(float4*)(outp + (size_t)d * SLEN + t0 + j * 4) = y;
    }
}

__global__ void __launch_bounds__(256, 1)
poly_attn_mma(const float* __restrict__ q, float* __restrict__ out) {
    extern __shared__ uint32_t sm[];
    const uint32_t sb = smem_u32addr(sm);
    const int tid = threadIdx.x;
    const int wid = tid >> 5, lane = tid & 31;
    const int tq = lane >> 2, tc = lane & 3;
    const int bh = blockIdx.y, mt = blockIdx.x;
    const int m0 = wid * 32;

    // ---- Q tile [256][64] -> bf16 hi/lo pairs, pair-interleaved u32 cols ----
    {
        const float4* qg = (const float4*)(q + ((size_t)bh * SLEN + (size_t)mt * BM) * DDIM);
#pragma unroll
        for (int r = 0; r < 16; r++) {
            int i4 = tid + r * 256;
            int row = i4 >> 4, pr = (i4 & 15) * 2;       // u32 cols pr, pr+1
            float4 x = qg[i4];
            float h0 = bfrt(x.x), h1 = bfrt(x.y), h2 = bfrt(x.z), h3 = bfrt(x.w);
            uint32_t hA = packbf(h1, h0), hB = packbf(h3, h2);
            uint32_t lA = packbf(x.y - h1, x.x - h0), lB = packbf(x.w - h3, x.z - h2);
            int base = row * LDQ2 + (pr & ~7) + (((pr >> 2) & 1) | ((pr & 2) << 1));
            sm[OF_QH + base] = hA; sm[OF_QH + base + 2] = hB;
            sm[OF_QL + base] = lA; sm[OF_QL + base + 2] = lB;
        }
    }

    // ---- async tile staging (layouts already baked in gmem) ----
    auto issue_tile = [&](int nt, int buf) {
        const uint32_t* gKH = g_KH + ((size_t)bh * SLEN + nt * BT) * 32;
        const uint32_t* gKL = g_KL + ((size_t)bh * SLEN + nt * BT) * 32;
        const float* gV = g_VT + (size_t)bh * DDIM * SLEN + nt * BT;
#pragma unroll
        for (int j = 0; j < 2; j++) {
            int cc = tid + j * 256;
            int row = cc >> 3, o4 = (cc & 7) * 4;
            cp16(sb + (uint32_t)(OF_KH + buf * BT * LDK2 + row * LDK2 + o4) * 4,
                 gKH + row * 32 + o4);
            cp16(sb + (uint32_t)(OF_KL + buf * BT * LDK2 + row * LDK2 + o4) * 4,
                 gKL + row * 32 + o4);
        }
#pragma unroll
        for (int j = 0; j < 4; j++) {
            int cc = tid + j * 256;
            int d = cc >> 4, kc = (cc & 15) * 4;
            cp16(sb + (uint32_t)(OF_V + buf * DDIM * LDVT + d * LDVT + kc) * 4,
                 gV + (size_t)d * SLEN + kc);
        }
        asm volatile("cp.async.commit_group;" ::: "memory");
    };

    issue_tile(0, 0);
    issue_tile(1, 1);
    asm volatile("cp.async.wait_group 1;" ::: "memory");
    __syncthreads();

    float oacc[2][8][4];
    float dl[2] = {0.f, 0.f}, dh[2] = {0.f, 0.f};
#pragma unroll
    for (int t = 0; t < 2; t++)
#pragma unroll
        for (int ct = 0; ct < 8; ct++)
#pragma unroll
            for (int j = 0; j < 4; j++) oacc[t][ct][j] = 0.f;

    const int qoffh0 = OF_QH + (m0 + tq) * LDQ2 + 2 * tc;
    const int qoffl0 = OF_QL + (m0 + tq) * LDQ2 + 2 * tc;

    for (int nt = 0; nt < NITER; nt++) {
        const int buf = nt & 1;
        const int KHo = OF_KH + buf * BT * LDK2;
        const int KLo = OF_KL + buf * BT * LDK2;
        const int Vo  = OF_V  + buf * DDIM * LDVT;

        // ---- GEMM1: S[32x64] = (qh+ql)(kh+kl)^T (drop ql*kl); uint2 frags ----
        float sacc[2][8][4];
#pragma unroll
        for (int t = 0; t < 2; t++)
#pragma unroll
            for (int ct = 0; ct < 8; ct++)
#pragma unroll
                for (int j = 0; j < 4; j++) sacc[t][ct][j] = 0.f;

#pragma unroll
        for (int ks = 0; ks < 4; ks++) {
            const int ko = ks * 8;
            uint2 ahL[2], ahH[2], alL[2], alH[2];   // (a0,a2) rows tq / (a1,a3) rows tq+8
#pragma unroll
            for (int t = 0; t < 2; t++) {
                const int oh = qoffh0 + t * 16 * LDQ2 + ko;
                const int ol = qoffl0 + t * 16 * LDQ2 + ko;
                ahL[t] = *(const uint2*)(sm + oh);
                ahH[t] = *(const uint2*)(sm + oh + 8 * LDQ2);
                alL[t] = *(const uint2*)(sm + ol);
                alH[t] = *(const uint2*)(sm + ol + 8 * LDQ2);
            }
#pragma unroll
            for (int ct = 0; ct < 8; ct++) {
                const int o = (8 * ct + tq) * LDK2 + ko + 2 * tc;
                uint2 bh2 = *(const uint2*)(sm + KHo + o);
                uint2 bl2 = *(const uint2*)(sm + KLo + o);
#pragma unroll
                for (int t = 0; t < 2; t++) {
                    mma16(sacc[t][ct], ahL[t].x, ahH[t].x, ahL[t].y, ahH[t].y, bh2.x, bh2.y);
                    mma16(sacc[t][ct], ahL[t].x, ahH[t].x, ahL[t].y, ahH[t].y, bl2.x, bl2.y);
                    mma16(sacc[t][ct], alL[t].x, alH[t].x, alL[t].y, alH[t].y, bh2.x, bh2.y);
                }
            }
        }

        // ---- fused epilogue + GEMM2: square group g, mma group g ----
        auto sq = [&](int g) {
#pragma unroll
            for (int t = 0; t < 2; t++) {
                sacc[t][g][0] = tf32_rna(sacc[t][g][0] * sacc[t][g][0]);
                sacc[t][g][1] = tf32_rna(sacc[t][g][1] * sacc[t][g][1]);
                sacc[t][g][2] = tf32_rna(sacc[t][g][2] * sacc[t][g][2]);
                sacc[t][g][3] = tf32_rna(sacc[t][g][3] * sacc[t][g][3]);
                dl[t] += sacc[t][g][0] + sacc[t][g][1];
                dh[t] += sacc[t][g][2] + sacc[t][g][3];
            }
        };
        sq(0);
#pragma unroll
        for (int g = 0; g < 8; g++) {
            const int vkb = Vo + 8 * g + 2 * tc + tq * LDVT;
#pragma unroll
            for (int ct = 0; ct < 8; ct++) {
                uint2 vv = *(const uint2*)(sm + vkb + 8 * ct * LDVT);
                mma8v(oacc[0][ct], sacc[0][g][0], sacc[0][g][2],
                      sacc[0][g][1], sacc[0][g][3], vv.x, vv.y);
                mma8v(oacc[1][ct], sacc[1][g][0], sacc[1][g][2],
                      sacc[1][g][1], sacc[1][g][3], vv.x, vv.y);
            }
            if (g < 7) sq(g + 1);
        }

        if (nt + 1 < NITER)
            asm volatile("cp.async.wait_group 0;" ::: "memory");
        __syncthreads();
        if (nt + 2 < NITER) issue_tile(nt + 2, buf);
    }

    // ---- denominator reduce over tc lanes; normalize and store ----
    float* og = out + ((size_t)bh * SLEN + (size_t)mt * BM + m0) * DDIM;
#pragma unroll
    for (int t = 0; t < 2; t++) {
        float l = dl[t], h = dh[t];
        l += __shfl_xor_sync(0xffffffffu, l, 1);
        l += __shfl_xor_sync(0xffffffffu, l, 2);
        h += __shfl_xor_sync(0xffffffffu, h, 1);
        h += __shfl_xor_sync(0xffffffffu, h, 2);
        const float il = 1.f / fmaxf(l, EPS_CLAMP);
        const float ih = 1.f / fmaxf(h, EPS_CLAMP);
#pragma unroll
        for (int ct = 0; ct < 8; ct++) {
            int dcol = 8 * ct + 2 * tc;
            *(float2*)(og + (size_t)(t * 16 + tq) * DDIM + dcol) =
                make_float2(oacc[t][ct][0] * il, oacc[t][ct][1] * il);
            *(float2*)(og + (size_t)(t * 16 + tq + 8) * DDIM + dcol) =
                make_float2(oacc[t][ct][2] * ih, oacc[t][ct][3] * ih);
        }
    }
}

extern "C" void kernel_launch(void* const* d_in, const int* in_sizes, int n_in,
                              void* d_out, int out_size) {
    (void)in_sizes; (void)n_in; (void)out_size;
    const float* q = (const float*)d_in[0];
    const float* k = (const float*)d_in[1];
    const float* v = (const float*)d_in[2];
    float* out = (float*)d_out;

    precompute_k<<<1024, 256>>>(k);                 // 4.19M elems / 16 per thread
    build_vt<<<dim3(SLEN / 32, NBH), 256>>>(v);

    cudaFuncSetAttribute(poly_attn_mma,
                         cudaFuncAttributeMaxDynamicSharedMemorySize, SMEM_BYTES);
    poly_attn_mma<<<dim3(SLEN / BM, NBH), 256, SMEM_BYTES>>>(q, out);
}

// round 13
// speedup vs baseline: 1.1481x; 1.1481x over previous
#include <cuda_runtime.h>
#include <cuda_bf16.h>
#include <cstdint>

// Polynomial attention deg-2, B=2 H=16 S=2048 D=64 fp32.
// GEMM1: bf16 2-term split, mma.m16n8k16. GEMM2: tf32 m16n8k8, A-frags direct
// from GEMM1 accumulator via key-permutation baked into V layout.
// K-split/V-round precomputed to global scratch; tiles staged via cp.async.
// BM=128 / 128 threads / 4 warps (warp owns 32 rows), BT=64, 2 CTAs per SM.

#define NBH 32
#define SLEN 2048
#define DDIM 64
#define BM 128
#define BT 64
#define NITER (SLEN / BT)
#define NTHREADS 128
#define EPS_CLAMP 1e-4f

#define LDQ2 36
#define LDK2 36
#define LDV 72

// smem offsets (4-byte units)
#define OF_QH 0
#define OF_QL (OF_QH + BM * LDQ2)
#define OF_KH (OF_QL + BM * LDQ2)          // [2][64][36] u32 (bf16 pairs)
#define OF_KL (OF_KH + 2 * BT * LDK2)
#define OF_V  (OF_KL + 2 * BT * LDK2)      // [2][64][72] f32 (rows permuted)
#define SMEM_U32 (OF_V + 2 * BT * LDV)
#define SMEM_BYTES (SMEM_U32 * 4)

// global scratch: packed bf16-pair splits of K, rna-rounded V
__device__ uint32_t g_KH[(size_t)NBH * SLEN * 32];
__device__ uint32_t g_KL[(size_t)NBH * SLEN * 32];
__device__ float    g_Vr[(size_t)NBH * SLEN * DDIM];

__device__ __forceinline__ float tf32_rna(float x) {
    uint32_t u;
    asm("cvt.rna.tf32.f32 %0, %1;" : "=r"(u) : "f"(x));
    return __uint_as_float(u);
}
__device__ __forceinline__ uint32_t packbf(float hi, float lo) {
    uint32_t u;
    asm("cvt.rn.bf16x2.f32 %0, %1, %2;" : "=r"(u) : "f"(hi), "f"(lo));
    return u;
}
__device__ __forceinline__ float bfrt(float x) {
    return __bfloat162float(__float2bfloat16(x));
}
__device__ __forceinline__ uint32_t smem_u32addr(const void* p) {
    uint32_t a;
    asm("{ .reg .u64 t; cvta.to.shared.u64 t, %1; cvt.u32.u64 %0, t; }"
        : "=r"(a) : "l"(p));
    return a;
}
__device__ __forceinline__ void cp16(uint32_t dst, const void* src) {
    asm volatile("cp.async.cg.shared.global [%0], [%1], 16;"
                 :: "r"(dst), "l"(src));
}
__device__ __forceinline__ void mma16(float* d, const uint32_t* a, const uint32_t* b) {
    asm("mma.sync.aligned.m16n8k16.row.col.f32.bf16.bf16.f32 "
        "{%0,%1,%2,%3}, {%4,%5,%6,%7}, {%8,%9}, {%0,%1,%2,%3};"
        : "+f"(d[0]), "+f"(d[1]), "+f"(d[2]), "+f"(d[3])
        : "r"(a[0]), "r"(a[1]), "r"(a[2]), "r"(a[3]), "r"(b[0]), "r"(b[1]));
}
__device__ __forceinline__ void mma8(float* d, const uint32_t* a, const uint32_t* b) {
    asm("mma.sync.aligned.m16n8k8.row.col.f32.tf32.tf32.f32 "
        "{%0,%1,%2,%3}, {%4,%5,%6,%7}, {%8,%9}, {%0,%1,%2,%3};"
        : "+f"(d[0]), "+f"(d[1]), "+f"(d[2]), "+f"(d[3])
        : "r"(a[0]), "r"(a[1]), "r"(a[2]), "r"(a[3]), "r"(b[0]), "r"(b[1]));
}

// ---- precompute: K -> (KH,KL) packed bf16 pairs, V -> rna-rounded f32 ----
__global__ void precompute_kv(const float* __restrict__ k,
                              const float* __restrict__ v) {
    size_t i = (size_t)blockIdx.x * blockDim.x + threadIdx.x;
    const float4* k4 = (const float4*)k;
    const float4* v4 = (const float4*)v;
    uint4 H[2], L[2];
    uint32_t* hp = (uint32_t*)H;
    uint32_t* lp = (uint32_t*)L;
#pragma unroll
    for (int r = 0; r < 4; r++) {
        float4 x = k4[i * 4 + r];
        float h0 = bfrt(x.x), h1 = bfrt(x.y), h2 = bfrt(x.z), h3 = bfrt(x.w);
        hp[r * 2 + 0] = packbf(h1, h0);
        hp[r * 2 + 1] = packbf(h3, h2);
        lp[r * 2 + 0] = packbf(x.y - h1, x.x - h0);
        lp[r * 2 + 1] = packbf(x.w - h3, x.z - h2);
    }
    ((uint4*)g_KH)[i * 2 + 0] = H[0];
    ((uint4*)g_KH)[i * 2 + 1] = H[1];
    ((uint4*)g_KL)[i * 2 + 0] = L[0];
    ((uint4*)g_KL)[i * 2 + 1] = L[1];
#pragma unroll
    for (int r = 0; r < 4; r++) {
        float4 y = v4[i * 4 + r];
        y.x = tf32_rna(y.x); y.y = tf32_rna(y.y);
        y.z = tf32_rna(y.z); y.w = tf32_rna(y.w);
        ((float4*)g_Vr)[i * 4 + r] = y;
    }
}

__global__ void __launch_bounds__(NTHREADS, 2)
poly_attn_mma(const float* __restrict__ q, float* __restrict__ out) {
    extern __shared__ uint32_t sm[];
    const uint32_t sb = smem_u32addr(sm);
    const int tid = threadIdx.x;
    const int wid = tid >> 5, lane = tid & 31;
    const int tq = lane >> 2, tc = lane & 3;
    const int bh = blockIdx.y, mt = blockIdx.x;
    const int m0 = wid * 32;

    // ---- Q tile [128][64] -> bf16 hi/lo pairs (once) ----
    {
        const float4* qg = (const float4*)(q + ((size_t)bh * SLEN + (size_t)mt * BM) * DDIM);
#pragma unroll
        for (int r = 0; r < 16; r++) {
            int i4 = tid + r * NTHREADS;
            int row = i4 >> 4, pr = (i4 & 15) * 2;
            float4 x = qg[i4];
            float h0 = bfrt(x.x), h1 = bfrt(x.y), h2 = bfrt(x.z), h3 = bfrt(x.w);
            *(uint2*)(sm + OF_QH + row * LDQ2 + pr) =
                make_uint2(packbf(h1, h0), packbf(h3, h2));
            *(uint2*)(sm + OF_QL + row * LDQ2 + pr) =
                make_uint2(packbf(x.y - h1, x.x - h0), packbf(x.w - h3, x.z - h2));
        }
    }

    // ---- async tile stage ----
    auto issue_tile = [&](int nt, int buf) {
        const uint32_t* gKH = g_KH + ((size_t)bh * SLEN + nt * BT) * 32;
        const uint32_t* gKL = g_KL + ((size_t)bh * SLEN + nt * BT) * 32;
        const float* gV = g_Vr + ((size_t)bh * SLEN + nt * BT) * DDIM;
#pragma unroll
        for (int j = 0; j < 4; j++) {
            int cc = tid + j * NTHREADS;
            int row = cc >> 3, o4 = (cc & 7) * 4;
            cp16(sb + (uint32_t)(OF_KH + buf * BT * LDK2 + row * LDK2 + o4) * 4,
                 gKH + row * 32 + o4);
            cp16(sb + (uint32_t)(OF_KL + buf * BT * LDK2 + row * LDK2 + o4) * 4,
                 gKL + row * 32 + o4);
        }
#pragma unroll
        for (int j = 0; j < 8; j++) {
            int cc = tid + j * NTHREADS;
            int row = cc >> 4, o4 = (cc & 15) * 4;
            int jj = row & 7;   // V row permutation (matches GEMM2 A-frag layout)
            int vrow = (row & ~7) | ((jj & 1) ? (4 + (jj >> 1)) : (jj >> 1));
            cp16(sb + (uint32_t)(OF_V + buf * BT * LDV + vrow * LDV + o4) * 4,
                 gV + row * DDIM + o4);
        }
        asm volatile("cp.async.commit_group;" ::: "memory");
    };

    issue_tile(0, 0);
    issue_tile(1, 1);
    asm volatile("cp.async.wait_group 1;" ::: "memory");   // tile 0 landed
    __syncthreads();

    float oacc[2][8][4];
    float dl[2] = {0.f, 0.f}, dh[2] = {0.f, 0.f};
#pragma unroll
    for (int t = 0; t < 2; t++)
#pragma unroll
        for (int ct = 0; ct < 8; ct++)
#pragma unroll
            for (int j = 0; j < 4; j++) oacc[t][ct][j] = 0.f;

    const int qoffh0 = OF_QH + (m0 + tq) * LDQ2 + tc;
    const int qoffl0 = OF_QL + (m0 + tq) * LDQ2 + tc;

    for (int nt = 0; nt < NITER; nt++) {
        const int buf = nt & 1;
        const int KHo = OF_KH + buf * BT * LDK2;
        const int KLo = OF_KL + buf * BT * LDK2;
        const int Vo  = OF_V  + buf * BT * LDV;

        // ---- GEMM1: S[32x64] = (qh+ql)(kh+kl)^T (drop ql*kl) ----
        float sacc[2][8][4];
#pragma unroll
        for (int t = 0; t < 2; t++)
#pragma unroll
            for (int ct = 0; ct < 8; ct++)
#pragma unroll
                for (int j = 0; j < 4; j++) sacc[t][ct][j] = 0.f;

#pragma unroll
        for (int ks = 0; ks < 4; ks++) {
            const int ko = ks * 8;
            uint32_t ah[2][4], al[2][4];
#pragma unroll
            for (int t = 0; t < 2; t++) {
                const int oh = qoffh0 + t * 16 * LDQ2 + ko;
                const int ol = qoffl0 + t * 16 * LDQ2 + ko;
                ah[t][0] = sm[oh];
                ah[t][1] = sm[oh + 8 * LDQ2];
                ah[t][2] = sm[oh + 4];
                ah[t][3] = sm[oh + 8 * LDQ2 + 4];
                al[t][0] = sm[ol];
                al[t][1] = sm[ol + 8 * LDQ2];
                al[t][2] = sm[ol + 4];
                al[t][3] = sm[ol + 8 * LDQ2 + 4];
            }
#pragma unroll
            for (int ct = 0; ct < 8; ct++) {
                const int o = (8 * ct + tq) * LDK2 + ko + tc;
                uint32_t bh2[2], bl2[2];
                bh2[0] = sm[KHo + o]; bh2[1] = sm[KHo + o + 4];
                bl2[0] = sm[KLo + o]; bl2[1] = sm[KLo + o + 4];
#pragma unroll
                for (int t = 0; t < 2; t++) {
                    mma16(sacc[t][ct], ah[t], bh2);
                    mma16(sacc[t][ct], ah[t], bl2);
                    mma16(sacc[t][ct], al[t], bh2);
                }
            }
        }

        // ---- epilogue: P = rna_tf32(S^2); denom partials ----
#pragma unroll
        for (int t = 0; t < 2; t++)
#pragma unroll
            for (int ct = 0; ct < 8; ct++) {
                sacc[t][ct][0] = tf32_rna(sacc[t][ct][0] * sacc[t][ct][0]);
                sacc[t][ct][1] = tf32_rna(sacc[t][ct][1] * sacc[t][ct][1]);
                sacc[t][ct][2] = tf32_rna(sacc[t][ct][2] * sacc[t][ct][2]);
                sacc[t][ct][3] = tf32_rna(sacc[t][ct][3] * sacc[t][ct][3]);
                dl[t] += sacc[t][ct][0] + sacc[t][ct][1];
                dh[t] += sacc[t][ct][2] + sacc[t][ct][3];
            }

        // ---- GEMM2 (tf32): O += P * V_perm; A-frag = acc regs {0,2,1,3} ----
#pragma unroll
        for (int g = 0; g < 8; g++) {
            uint32_t a[2][4];
#pragma unroll
            for (int t = 0; t < 2; t++) {
                a[t][0] = __float_as_uint(sacc[t][g][0]);
                a[t][1] = __float_as_uint(sacc[t][g][2]);
                a[t][2] = __float_as_uint(sacc[t][g][1]);
                a[t][3] = __float_as_uint(sacc[t][g][3]);
            }
            const int vk = Vo + (8 * g + tc) * LDV + tq;
#pragma unroll
            for (int ct = 0; ct < 8; ct++) {
                uint32_t vb[2];
                vb[0] = sm[vk + 8 * ct];
                vb[1] = sm[vk + 4 * LDV + 8 * ct];
                mma8(oacc[0][ct], a[0], vb);
                mma8(oacc[1][ct], a[1], vb);
            }
        }

        if (nt + 1 < NITER)
            asm volatile("cp.async.wait_group 0;" ::: "memory");  // tile nt+1 landed
        __syncthreads();
        if (nt + 2 < NITER) issue_tile(nt + 2, buf);
    }

    // ---- denominator reduce over tc lanes; normalize and store ----
    float* og = out + ((size_t)bh * SLEN + (size_t)mt * BM + m0) * DDIM;
#pragma unroll
    for (int t = 0; t < 2; t++) {
        float l = dl[t], h = dh[t];
        l += __shfl_xor_sync(0xffffffffu, l, 1);
        l += __shfl_xor_sync(0xffffffffu, l, 2);
        h += __shfl_xor_sync(0xffffffffu, h, 1);
        h += __shfl_xor_sync(0xffffffffu, h, 2);
        const float il = 1.f / fmaxf(l, EPS_CLAMP);
        const float ih = 1.f / fmaxf(h, EPS_CLAMP);
#pragma unroll
        for (int ct = 0; ct < 8; ct++) {
            int dcol = 8 * ct + 2 * tc;
            *(float2*)(og + (size_t)(t * 16 + tq) * DDIM + dcol) =
                make_float2(oacc[t][ct][0] * il, oacc[t][ct][1] * il);
            *(float2*)(og + (size_t)(t * 16 + tq + 8) * DDIM + dcol) =
                make_float2(oacc[t][ct][2] * ih, oacc[t][ct][3] * ih);
        }
    }
}

extern "C" void kernel_launch(void* const* d_in, const int* in_sizes, int n_in,
                              void* d_out, int out_size) {
    (void)in_sizes; (void)n_in; (void)out_size;
    const float* q = (const float*)d_in[0];
    const float* k = (const float*)d_in[1];
    const float* v = (const float*)d_in[2];
    float* out = (float*)d_out;

    precompute_kv<<<1024, 256>>>(k, v);

    cudaFuncSetAttribute(poly_attn_mma,
                         cudaFuncAttributeMaxDynamicSharedMemorySize, SMEM_BYTES);
    poly_attn_mma<<<dim3(SLEN / BM, NBH), NTHREADS, SMEM_BYTES>>>(q, out);
}

// round 14
// speedup vs baseline: 1.1685x; 1.0178x over previous
#include <cuda_runtime.h>
#include <cuda_bf16.h>
#include <cstdint>

// Polynomial attention deg-2, B=2 H=16 S=2048 D=64 fp32.
// GEMM1: bf16 2-term split, mma.m16n8k16. GEMM2: tf32 m16n8k8, A-frags direct
// from GEMM1 accumulator (key-perm baked into V layout). Precomputed K/V scratch.
// 3 CTAs/SM x 4 warps (warp owns 16 rows), BT=64, single-buffer smem with
// time-staggered cp.async (K overlaps GEMM2, V overlaps GEMM1).

#define NBH 32
#define SLEN 2048
#define DDIM 64
#define BM 64
#define BT 64
#define NITER (SLEN / BT)
#define NTHREADS 128
#define EPS_CLAMP 1e-4f

#define LDQ2 36
#define LDK2 36
#define LDV 72

// smem offsets (4-byte units), single-buffered
#define OF_QH 0
#define OF_QL (OF_QH + BM * LDQ2)          // 2304
#define OF_KH (OF_QL + BM * LDQ2)          // [64][36] u32
#define OF_KL (OF_KH + BT * LDK2)
#define OF_V  (OF_KL + BT * LDK2)          // [64][72] f32 (rows permuted)
#define SMEM_U32 (OF_V + BT * LDV)
#define SMEM_BYTES (SMEM_U32 * 4)          // 55296 B

// global scratch: packed bf16-pair splits of K, rna-rounded V
__device__ uint32_t g_KH[(size_t)NBH * SLEN * 32];
__device__ uint32_t g_KL[(size_t)NBH * SLEN * 32];
__device__ float    g_Vr[(size_t)NBH * SLEN * DDIM];

__device__ __forceinline__ float tf32_rna(float x) {
    uint32_t u;
    asm("cvt.rna.tf32.f32 %0, %1;" : "=r"(u) : "f"(x));
    return __uint_as_float(u);
}
__device__ __forceinline__ uint32_t packbf(float hi, float lo) {
    uint32_t u;
    asm("cvt.rn.bf16x2.f32 %0, %1, %2;" : "=r"(u) : "f"(hi), "f"(lo));
    return u;
}
__device__ __forceinline__ float bfrt(float x) {
    return __bfloat162float(__float2bfloat16(x));
}
__device__ __forceinline__ uint32_t smem_u32addr(const void* p) {
    uint32_t a;
    asm("{ .reg .u64 t; cvta.to.shared.u64 t, %1; cvt.u32.u64 %0, t; }"
        : "=r"(a) : "l"(p));
    return a;
}
__device__ __forceinline__ void cp16(uint32_t dst, const void* src) {
    asm volatile("cp.async.cg.shared.global [%0], [%1], 16;"
                 :: "r"(dst), "l"(src));
}
__device__ __forceinline__ void mma16(float* d, const uint32_t* a, const uint32_t* b) {
    asm("mma.sync.aligned.m16n8k16.row.col.f32.bf16.bf16.f32 "
        "{%0,%1,%2,%3}, {%4,%5,%6,%7}, {%8,%9}, {%0,%1,%2,%3};"
        : "+f"(d[0]), "+f"(d[1]), "+f"(d[2]), "+f"(d[3])
        : "r"(a[0]), "r"(a[1]), "r"(a[2]), "r"(a[3]), "r"(b[0]), "r"(b[1]));
}
__device__ __forceinline__ void mma8(float* d, const uint32_t* a, const uint32_t* b) {
    asm("mma.sync.aligned.m16n8k8.row.col.f32.tf32.tf32.f32 "
        "{%0,%1,%2,%3}, {%4,%5,%6,%7}, {%8,%9}, {%0,%1,%2,%3};"
        : "+f"(d[0]), "+f"(d[1]), "+f"(d[2]), "+f"(d[3])
        : "r"(a[0]), "r"(a[1]), "r"(a[2]), "r"(a[3]), "r"(b[0]), "r"(b[1]));
}

// ---- precompute: K -> (KH,KL) packed bf16 pairs, V -> rna-rounded f32 ----
__global__ void precompute_kv(const float* __restrict__ k,
                              const float* __restrict__ v) {
    size_t i = (size_t)blockIdx.x * blockDim.x + threadIdx.x;
    const float4* k4 = (const float4*)k;
    const float4* v4 = (const float4*)v;
    uint4 H[2], L[2];
    uint32_t* hp = (uint32_t*)H;
    uint32_t* lp = (uint32_t*)L;
#pragma unroll
    for (int r = 0; r < 4; r++) {
        float4 x = k4[i * 4 + r];
        float h0 = bfrt(x.x), h1 = bfrt(x.y), h2 = bfrt(x.z), h3 = bfrt(x.w);
        hp[r * 2 + 0] = packbf(h1, h0);
        hp[r * 2 + 1] = packbf(h3, h2);
        lp[r * 2 + 0] = packbf(x.y - h1, x.x - h0);
        lp[r * 2 + 1] = packbf(x.w - h3, x.z - h2);
    }
    ((uint4*)g_KH)[i * 2 + 0] = H[0];
    ((uint4*)g_KH)[i * 2 + 1] = H[1];
    ((uint4*)g_KL)[i * 2 + 0] = L[0];
    ((uint4*)g_KL)[i * 2 + 1] = L[1];
#pragma unroll
    for (int r = 0; r < 4; r++) {
        float4 y = v4[i * 4 + r];
        y.x = tf32_rna(y.x); y.y = tf32_rna(y.y);
        y.z = tf32_rna(y.z); y.w = tf32_rna(y.w);
        ((float4*)g_Vr)[i * 4 + r] = y;
    }
}

__global__ void __launch_bounds__(NTHREADS, 3)
poly_attn_mma(const float* __restrict__ q, float* __restrict__ out) {
    extern __shared__ uint32_t sm[];
    const uint32_t sb = smem_u32addr(sm);
    const int tid = threadIdx.x;
    const int wid = tid >> 5, lane = tid & 31;
    const int tq = lane >> 2, tc = lane & 3;
    const int bh = blockIdx.y, mt = blockIdx.x;
    const int m0 = wid * 16;                 // warp owns rows m0..m0+15

    // ---- async loaders (single-buffered; pipelined in time) ----
    auto issue_K = [&](int nt) {
        const uint32_t* gKH = g_KH + ((size_t)bh * SLEN + nt * BT) * 32;
        const uint32_t* gKL = g_KL + ((size_t)bh * SLEN + nt * BT) * 32;
#pragma unroll
        for (int j = 0; j < 4; j++) {
            int cc = tid + j * NTHREADS;
            int row = cc >> 3, o4 = (cc & 7) * 4;
            cp16(sb + (uint32_t)(OF_KH + row * LDK2 + o4) * 4, gKH + row * 32 + o4);
            cp16(sb + (uint32_t)(OF_KL + row * LDK2 + o4) * 4, gKL + row * 32 + o4);
        }
        asm volatile("cp.async.commit_group;" ::: "memory");
    };
    auto issue_V = [&](int nt) {
        const float* gV = g_Vr + ((size_t)bh * SLEN + nt * BT) * DDIM;
#pragma unroll
        for (int j = 0; j < 8; j++) {
            int cc = tid + j * NTHREADS;
            int row = cc >> 4, o4 = (cc & 15) * 4;
            int jj = row & 7;   // V row permutation (matches GEMM2 A-frag layout)
            int vrow = (row & ~7) | ((jj & 1) ? (4 + (jj >> 1)) : (jj >> 1));
            cp16(sb + (uint32_t)(OF_V + vrow * LDV + o4) * 4, gV + row * DDIM + o4);
        }
        asm volatile("cp.async.commit_group;" ::: "memory");
    };

    issue_K(0);
    issue_V(0);

    // ---- Q tile [64][64] -> bf16 hi/lo pairs (overlaps prologue cp.async) ----
    {
        const float4* qg = (const float4*)(q + ((size_t)bh * SLEN + (size_t)mt * BM) * DDIM);
#pragma unroll
        for (int r = 0; r < 8; r++) {
            int i4 = tid + r * NTHREADS;
            int row = i4 >> 4, pr = (i4 & 15) * 2;
            float4 x = qg[i4];
            float h0 = bfrt(x.x), h1 = bfrt(x.y), h2 = bfrt(x.z), h3 = bfrt(x.w);
            *(uint2*)(sm + OF_QH + row * LDQ2 + pr) =
                make_uint2(packbf(h1, h0), packbf(h3, h2));
            *(uint2*)(sm + OF_QL + row * LDQ2 + pr) =
                make_uint2(packbf(x.y - h1, x.x - h0), packbf(x.w - h3, x.z - h2));
        }
    }
    asm volatile("cp.async.wait_group 0;" ::: "memory");
    __syncthreads();

    float oacc[8][4];
    float dl = 0.f, dh = 0.f;
#pragma unroll
    for (int ct = 0; ct < 8; ct++)
#pragma unroll
        for (int j = 0; j < 4; j++) oacc[ct][j] = 0.f;

    const int qoffh0 = OF_QH + (m0 + tq) * LDQ2 + tc;
    const int qoffl0 = OF_QL + (m0 + tq) * LDQ2 + tc;

    for (int nt = 0; nt < NITER; nt++) {
        // ---- GEMM1: S[16x64] = (qh+ql)(kh+kl)^T (drop ql*kl) ----
        float sacc[8][4];
#pragma unroll
        for (int ct = 0; ct < 8; ct++)
#pragma unroll
            for (int j = 0; j < 4; j++) sacc[ct][j] = 0.f;

#pragma unroll
        for (int ks = 0; ks < 4; ks++) {
            const int ko = ks * 8;
            uint32_t ah[4], al[4];
            {
                const int oh = qoffh0 + ko;
                const int ol = qoffl0 + ko;
                ah[0] = sm[oh];
                ah[1] = sm[oh + 8 * LDQ2];
                ah[2] = sm[oh + 4];
                ah[3] = sm[oh + 8 * LDQ2 + 4];
                al[0] = sm[ol];
                al[1] = sm[ol + 8 * LDQ2];
                al[2] = sm[ol + 4];
                al[3] = sm[ol + 8 * LDQ2 + 4];
            }
#pragma unroll
            for (int ct = 0; ct < 8; ct++) {
                const int o = OF_KH + (8 * ct + tq) * LDK2 + ko + tc;
                const int o2 = OF_KL + (8 * ct + tq) * LDK2 + ko + tc;
                uint32_t bh2[2], bl2[2];
                bh2[0] = sm[o];  bh2[1] = sm[o + 4];
                bl2[0] = sm[o2]; bl2[1] = sm[o2 + 4];
                mma16(sacc[ct], ah, bh2);
                mma16(sacc[ct], ah, bl2);
                mma16(sacc[ct], al, bh2);
            }
        }

        // V(nt) landed (issued during prev iter / prologue); K fully consumed.
        asm volatile("cp.async.wait_group 0;" ::: "memory");
        __syncthreads();
        if (nt + 1 < NITER) issue_K(nt + 1);   // lands during epilogue+GEMM2

        // ---- epilogue: P = rna_tf32(S^2); denom partials ----
#pragma unroll
        for (int ct = 0; ct < 8; ct++) {
            sacc[ct][0] = tf32_rna(sacc[ct][0] * sacc[ct][0]);
            sacc[ct][1] = tf32_rna(sacc[ct][1] * sacc[ct][1]);
            sacc[ct][2] = tf32_rna(sacc[ct][2] * sacc[ct][2]);
            sacc[ct][3] = tf32_rna(sacc[ct][3] * sacc[ct][3]);
            dl += sacc[ct][0] + sacc[ct][1];
            dh += sacc[ct][2] + sacc[ct][3];
        }

        // ---- GEMM2 (tf32): O[16x64] += P * V_perm; A-frag = acc {0,2,1,3} ----
#pragma unroll
        for (int g = 0; g < 8; g++) {
            uint32_t a[4];
            a[0] = __float_as_uint(sacc[g][0]);
            a[1] = __float_as_uint(sacc[g][2]);
            a[2] = __float_as_uint(sacc[g][1]);
            a[3] = __float_as_uint(sacc[g][3]);
            const int vk = OF_V + (8 * g + tc) * LDV + tq;
#pragma unroll
            for (int ct = 0; ct < 8; ct++) {
                uint32_t vb[2];
                vb[0] = sm[vk + 8 * ct];
                vb[1] = sm[vk + 4 * LDV + 8 * ct];
                mma8(oacc[ct], a, vb);
            }
        }

        if (nt + 1 < NITER) {
            asm volatile("cp.async.wait_group 0;" ::: "memory"); // K(nt+1) landed
            __syncthreads();    // all warps done with V(nt); K(nt+1) visible
            issue_V(nt + 1);    // lands during next GEMM1
        }
    }

    // ---- denominator reduce over tc lanes; normalize and store ----
    dl += __shfl_xor_sync(0xffffffffu, dl, 1);
    dl += __shfl_xor_sync(0xffffffffu, dl, 2);
    dh += __shfl_xor_sync(0xffffffffu, dh, 1);
    dh += __shfl_xor_sync(0xffffffffu, dh, 2);
    const float il = 1.f / fmaxf(dl, EPS_CLAMP);
    const float ih = 1.f / fmaxf(dh, EPS_CLAMP);

    float* og = out + ((size_t)bh * SLEN + (size_t)mt * BM + m0) * DDIM;
#pragma unroll
    for (int ct = 0; ct < 8; ct++) {
        int dcol = 8 * ct + 2 * tc;
        *(float2*)(og + (size_t)tq * DDIM + dcol) =
            make_float2(oacc[ct][0] * il, oacc[ct][1] * il);
        *(float2*)(og + (size_t)(tq + 8) * DDIM + dcol) =
            make_float2(oacc[ct][2] * ih, oacc[ct][3] * ih);
    }
}

extern "C" void kernel_launch(void* const* d_in, const int* in_sizes, int n_in,
                              void* d_out, int out_size) {
    (void)in_sizes; (void)n_in; (void)out_size;
    const float* q = (const float*)d_in[0];
    const float* k = (const float*)d_in[1];
    const float* v = (const float*)d_in[2];
    float* out = (float*)d_out;

    precompute_kv<<<1024, 256>>>(k, v);

    cudaFuncSetAttribute(poly_attn_mma,
                         cudaFuncAttributeMaxDynamicSharedMemorySize, SMEM_BYTES);
    poly_attn_mma<<<dim3(SLEN / BM, NBH), NTHREADS, SMEM_BYTES>>>(q, out);
}

// round 15
// speedup vs baseline: 1.1795x; 1.0093x over previous
#include <cuda_runtime.h>
#include <cuda_bf16.h>
#include <cstdint>

// Polynomial attention deg-2, B=2 H=16 S=2048 D=64 fp32.
// GEMM1: bf16 2-term split, mma.m16n8k16 -- issued in 3 passes (hh, hl, lh)
//        per k-step so same-accumulator mma are 16 apart (latency hiding).
// GEMM2: tf32 m16n8k8, A-frags direct from GEMM1 accumulator via key-perm
//        baked into V layout. Precomputed K/V scratch, cp.async staging.
// BM=256 (warp owns 32 rows), BT=64, double-buffered, 256 threads, 1 CTA/SM.

#define NBH 32
#define SLEN 2048
#define DDIM 64
#define BM 256
#define BT 64
#define NITER (SLEN / BT)
#define EPS_CLAMP 1e-4f

#define LDQ2 36
#define LDK2 36
#define LDV 72

// smem offsets (4-byte units)
#define OF_QH 0
#define OF_QL (OF_QH + BM * LDQ2)
#define OF_KH (OF_QL + BM * LDQ2)          // [2][64][36] u32 (bf16 pairs)
#define OF_KL (OF_KH + 2 * BT * LDK2)
#define OF_V  (OF_KL + 2 * BT * LDK2)      // [2][64][72] f32 (rows permuted)
#define SMEM_U32 (OF_V + 2 * BT * LDV)
#define SMEM_BYTES (SMEM_U32 * 4)

// global scratch: packed bf16-pair splits of K, rna-rounded V
__device__ uint32_t g_KH[(size_t)NBH * SLEN * 32];
__device__ uint32_t g_KL[(size_t)NBH * SLEN * 32];
__device__ float    g_Vr[(size_t)NBH * SLEN * DDIM];

__device__ __forceinline__ float tf32_rna(float x) {
    uint32_t u;
    asm("cvt.rna.tf32.f32 %0, %1;" : "=r"(u) : "f"(x));
    return __uint_as_float(u);
}
__device__ __forceinline__ uint32_t packbf(float hi, float lo) {
    uint32_t u;
    asm("cvt.rn.bf16x2.f32 %0, %1, %2;" : "=r"(u) : "f"(hi), "f"(lo));
    return u;
}
__device__ __forceinline__ float bfrt(float x) {
    return __bfloat162float(__float2bfloat16(x));
}
__device__ __forceinline__ uint32_t smem_u32addr(const void* p) {
    uint32_t a;
    asm("{ .reg .u64 t; cvta.to.shared.u64 t, %1; cvt.u32.u64 %0, t; }"
        : "=r"(a) : "l"(p));
    return a;
}
__device__ __forceinline__ void cp16(uint32_t dst, const void* src) {
    asm volatile("cp.async.cg.shared.global [%0], [%1], 16;"
                 :: "r"(dst), "l"(src));
}
__device__ __forceinline__ void mma16(float* d, const uint32_t* a, const uint32_t* b) {
    asm("mma.sync.aligned.m16n8k16.row.col.f32.bf16.bf16.f32 "
        "{%0,%1,%2,%3}, {%4,%5,%6,%7}, {%8,%9}, {%0,%1,%2,%3};"
        : "+f"(d[0]), "+f"(d[1]), "+f"(d[2]), "+f"(d[3])
        : "r"(a[0]), "r"(a[1]), "r"(a[2]), "r"(a[3]), "r"(b[0]), "r"(b[1]));
}
__device__ __forceinline__ void mma8(float* d, const uint32_t* a, const uint32_t* b) {
    asm("mma.sync.aligned.m16n8k8.row.col.f32.tf32.tf32.f32 "
        "{%0,%1,%2,%3}, {%4,%5,%6,%7}, {%8,%9}, {%0,%1,%2,%3};"
        : "+f"(d[0]), "+f"(d[1]), "+f"(d[2]), "+f"(d[3])
        : "r"(a[0]), "r"(a[1]), "r"(a[2]), "r"(a[3]), "r"(b[0]), "r"(b[1]));
}

// ---- precompute: K -> (KH,KL) packed bf16 pairs, V -> rna-rounded f32 ----
__global__ void precompute_kv(const float* __restrict__ k,
                              const float* __restrict__ v) {
    size_t i = (size_t)blockIdx.x * blockDim.x + threadIdx.x;
    const float4* k4 = (const float4*)k;
    const float4* v4 = (const float4*)v;
    uint4 H[2], L[2];
    uint32_t* hp = (uint32_t*)H;
    uint32_t* lp = (uint32_t*)L;
#pragma unroll
    for (int r = 0; r < 4; r++) {
        float4 x = k4[i * 4 + r];
        float h0 = bfrt(x.x), h1 = bfrt(x.y), h2 = bfrt(x.z), h3 = bfrt(x.w);
        hp[r * 2 + 0] = packbf(h1, h0);
        hp[r * 2 + 1] = packbf(h3, h2);
        lp[r * 2 + 0] = packbf(x.y - h1, x.x - h0);
        lp[r * 2 + 1] = packbf(x.w - h3, x.z - h2);
    }
    ((uint4*)g_KH)[i * 2 + 0] = H[0];
    ((uint4*)g_KH)[i * 2 + 1] = H[1];
    ((uint4*)g_KL)[i * 2 + 0] = L[0];
    ((uint4*)g_KL)[i * 2 + 1] = L[1];
#pragma unroll
    for (int r = 0; r < 4; r++) {
        float4 y = v4[i * 4 + r];
        y.x = tf32_rna(y.x); y.y = tf32_rna(y.y);
        y.z = tf32_rna(y.z); y.w = tf32_rna(y.w);
        ((float4*)g_Vr)[i * 4 + r] = y;
    }
}

__global__ void __launch_bounds__(256, 1)
poly_attn_mma(const float* __restrict__ q, float* __restrict__ out) {
    extern __shared__ uint32_t sm[];
    const uint32_t sb = smem_u32addr(sm);
    const int tid = threadIdx.x;
    const int wid = tid >> 5, lane = tid & 31;
    const int tq = lane >> 2, tc = lane & 3;
    const int bh = blockIdx.y, mt = blockIdx.x;
    const int m0 = wid * 32;

    // ---- Q tile [256][64] -> bf16 hi/lo pairs (once) ----
    {
        const float4* qg = (const float4*)(q + ((size_t)bh * SLEN + (size_t)mt * BM) * DDIM);
#pragma unroll
        for (int r = 0; r < 16; r++) {
            int i4 = tid + r * 256;
            int row = i4 >> 4, pr = (i4 & 15) * 2;
            float4 x = qg[i4];
            float h0 = bfrt(x.x), h1 = bfrt(x.y), h2 = bfrt(x.z), h3 = bfrt(x.w);
            *(uint2*)(sm + OF_QH + row * LDQ2 + pr) =
                make_uint2(packbf(h1, h0), packbf(h3, h2));
            *(uint2*)(sm + OF_QL + row * LDQ2 + pr) =
                make_uint2(packbf(x.y - h1, x.x - h0), packbf(x.w - h3, x.z - h2));
        }
    }

    // ---- async tile stage ----
    auto issue_tile = [&](int nt, int buf) {
        const uint32_t* gKH = g_KH + ((size_t)bh * SLEN + nt * BT) * 32;
        const uint32_t* gKL = g_KL + ((size_t)bh * SLEN + nt * BT) * 32;
        const float* gV = g_Vr + ((size_t)bh * SLEN + nt * BT) * DDIM;
#pragma unroll
        for (int j = 0; j < 2; j++) {
            int cc = tid + j * 256;
            int row = cc >> 3, o4 = (cc & 7) * 4;
            cp16(sb + (uint32_t)(OF_KH + buf * BT * LDK2 + row * LDK2 + o4) * 4,
                 gKH + row * 32 + o4);
            cp16(sb + (uint32_t)(OF_KL + buf * BT * LDK2 + row * LDK2 + o4) * 4,
                 gKL + row * 32 + o4);
        }
#pragma unroll
        for (int j = 0; j < 4; j++) {
            int cc = tid + j * 256;
            int row = cc >> 4, o4 = (cc & 15) * 4;
            int jj = row & 7;   // V row permutation (matches GEMM2 A-frag layout)
            int vrow = (row & ~7) | ((jj & 1) ? (4 + (jj >> 1)) : (jj >> 1));
            cp16(sb + (uint32_t)(OF_V + buf * BT * LDV + vrow * LDV + o4) * 4,
                 gV + row * DDIM + o4);
        }
        asm volatile("cp.async.commit_group;" ::: "memory");
    };

    issue_tile(0, 0);
    issue_tile(1, 1);
    asm volatile("cp.async.wait_group 1;" ::: "memory");   // tile 0 landed
    __syncthreads();

    float oacc[2][8][4];
    float dl[2] = {0.f, 0.f}, dh[2] = {0.f, 0.f};
#pragma unroll
    for (int t = 0; t < 2; t++)
#pragma unroll
        for (int ct = 0; ct < 8; ct++)
#pragma unroll
            for (int j = 0; j < 4; j++) oacc[t][ct][j] = 0.f;

    const int qoffh0 = OF_QH + (m0 + tq) * LDQ2 + tc;
    const int qoffl0 = OF_QL + (m0 + tq) * LDQ2 + tc;

    for (int nt = 0; nt < NITER; nt++) {
        const int buf = nt & 1;
        const int KHo = OF_KH + buf * BT * LDK2;
        const int KLo = OF_KL + buf * BT * LDK2;
        const int Vo  = OF_V  + buf * BT * LDV;

        // ---- GEMM1: S[32x64], 3 passes per ks (same-acc distance = 16) ----
        float sacc[2][8][4];
#pragma unroll
        for (int t = 0; t < 2; t++)
#pragma unroll
            for (int ct = 0; ct < 8; ct++)
#pragma unroll
                for (int j = 0; j < 4; j++) sacc[t][ct][j] = 0.f;

#pragma unroll
        for (int ks = 0; ks < 4; ks++) {
            const int ko = ks * 8;
            uint32_t ah[2][4], al[2][4];
#pragma unroll
            for (int t = 0; t < 2; t++) {
                const int oh = qoffh0 + t * 16 * LDQ2 + ko;
                const int ol = qoffl0 + t * 16 * LDQ2 + ko;
                ah[t][0] = sm[oh];
                ah[t][1] = sm[oh + 8 * LDQ2];
                ah[t][2] = sm[oh + 4];
                ah[t][3] = sm[oh + 8 * LDQ2 + 4];
                al[t][0] = sm[ol];
                al[t][1] = sm[ol + 8 * LDQ2];
                al[t][2] = sm[ol + 4];
                al[t][3] = sm[ol + 8 * LDQ2 + 4];
            }
            uint32_t bh2[8][2];
            // pass 1: hh (load + cache bh2)
#pragma unroll
            for (int ct = 0; ct < 8; ct++) {
                const int o = KHo + (8 * ct + tq) * LDK2 + ko + tc;
                bh2[ct][0] = sm[o]; bh2[ct][1] = sm[o + 4];
                mma16(sacc[0][ct], ah[0], bh2[ct]);
                mma16(sacc[1][ct], ah[1], bh2[ct]);
            }
            // pass 2: hl (transient bl2)
#pragma unroll
            for (int ct = 0; ct < 8; ct++) {
                const int o = KLo + (8 * ct + tq) * LDK2 + ko + tc;
                uint32_t bl2[2];
                bl2[0] = sm[o]; bl2[1] = sm[o + 4];
                mma16(sacc[0][ct], ah[0], bl2);
                mma16(sacc[1][ct], ah[1], bl2);
            }
            // pass 3: lh (bh2 from registers)
#pragma unroll
            for (int ct = 0; ct < 8; ct++) {
                mma16(sacc[0][ct], al[0], bh2[ct]);
                mma16(sacc[1][ct], al[1], bh2[ct]);
            }
        }

        // ---- epilogue: P = rna_tf32(S^2); denom partials ----
#pragma unroll
        for (int t = 0; t < 2; t++)
#pragma unroll
            for (int ct = 0; ct < 8; ct++) {
                sacc[t][ct][0] = tf32_rna(sacc[t][ct][0] * sacc[t][ct][0]);
                sacc[t][ct][1] = tf32_rna(sacc[t][ct][1] * sacc[t][ct][1]);
                sacc[t][ct][2] = tf32_rna(sacc[t][ct][2] * sacc[t][ct][2]);
                sacc[t][ct][3] = tf32_rna(sacc[t][ct][3] * sacc[t][ct][3]);
                dl[t] += sacc[t][ct][0] + sacc[t][ct][1];
                dh[t] += sacc[t][ct][2] + sacc[t][ct][3];
            }

        // ---- GEMM2 (tf32): O += P * V_perm; A-frag = acc regs {0,2,1,3} ----
#pragma unroll
        for (int g = 0; g < 8; g++) {
            uint32_t a[2][4];
#pragma unroll
            for (int t = 0; t < 2; t++) {
                a[t][0] = __float_as_uint(sacc[t][g][0]);
                a[t][1] = __float_as_uint(sacc[t][g][2]);
                a[t][2] = __float_as_uint(sacc[t][g][1]);
                a[t][3] = __float_as_uint(sacc[t][g][3]);
            }
            const int vk = Vo + (8 * g + tc) * LDV + tq;
#pragma unroll
            for (int ct = 0; ct < 8; ct++) {
                uint32_t vb[2];
                vb[0] = sm[vk + 8 * ct];
                vb[1] = sm[vk + 4 * LDV + 8 * ct];
                mma8(oacc[0][ct], a[0], vb);
                mma8(oacc[1][ct], a[1], vb);
            }
        }

        if (nt + 1 < NITER)
            asm volatile("cp.async.wait_group 0;" ::: "memory");  // tile nt+1 landed
        __syncthreads();
        if (nt + 2 < NITER) issue_tile(nt + 2, buf);
    }

    // ---- denominator reduce over tc lanes; normalize and store ----
    float* og = out + ((size_t)bh * SLEN + (size_t)mt * BM + m0) * DDIM;
#pragma unroll
    for (int t = 0; t < 2; t++) {
        float l = dl[t], h = dh[t];
        l += __shfl_xor_sync(0xffffffffu, l, 1);
        l += __shfl_xor_sync(0xffffffffu, l, 2);
        h += __shfl_xor_sync(0xffffffffu, h, 1);
        h += __shfl_xor_sync(0xffffffffu, h, 2);
        const float il = 1.f / fmaxf(l, EPS_CLAMP);
        const float ih = 1.f / fmaxf(h, EPS_CLAMP);
#pragma unroll
        for (int ct = 0; ct < 8; ct++) {
            int dcol = 8 * ct + 2 * tc;
            *(float2*)(og + (size_t)(t * 16 + tq) * DDIM + dcol) =
                make_float2(oacc[t][ct][0] * il, oacc[t][ct][1] * il);
            *(float2*)(og + (size_t)(t * 16 + tq + 8) * DDIM + dcol) =
                make_float2(oacc[t][ct][2] * ih, oacc[t][ct][3] * ih);
        }
    }
}

extern "C" void kernel_launch(void* const* d_in, const int* in_sizes, int n_in,
                              void* d_out, int out_size) {
    (void)in_sizes; (void)n_in; (void)out_size;
    const float* q = (const float*)d_in[0];
    const float* k = (const float*)d_in[1];
    const float* v = (const float*)d_in[2];
    float* out = (float*)d_out;

    precompute_kv<<<1024, 256>>>(k, v);

    cudaFuncSetAttribute(poly_attn_mma,
                         cudaFuncAttributeMaxDynamicSharedMemorySize, SMEM_BYTES);
    poly_attn_mma<<<dim3(SLEN / BM, NBH), 256, SMEM_BYTES>>>(q, out);
}